// round 2
// baseline (speedup 1.0000x reference)
#include <cuda_runtime.h>
#include <math.h>
#include <stdint.h>

#define N_PTS 32768
#define D_DIM 128
#define K_CB  1024
#define ND    (N_PTS*D_DIM)     /* 4194304  */
#define NK    ((size_t)N_PTS*K_CB) /* 33554432 */

/* ---------------- persistent device scratch (no allocs allowed) ------------- */
__device__ float    g_xn[ND];            /* normalized x          16 MB  */
__device__ float    g_cn[K_CB*D_DIM];    /* normalized codebook   512 KB */
__device__ float    g_cos[N_PTS*K_CB];   /* cosine sims           134 MB */
__device__ float    g_lse[N_PTS];        /* per-row logsumexp of logits  */
__device__ double   g_u[K_CB];           /* row-sum accumulator          */
__device__ double   g_a[K_CB];           /* row scaling factor           */
__device__ double   g_b[N_PTS];          /* col scaling factor           */
__device__ unsigned g_omin, g_omax;      /* ordered-uint encoded min/max */
__device__ float    g_mid, g_amp;        /* centering constants          */
__device__ double   g_loss;              /* loss accumulator             */
__device__ int      g_idx[N_PTS];        /* argmax indices               */

/* ---------------- helpers --------------------------------------------------- */
__device__ __forceinline__ unsigned ford(float f) {
    unsigned u = __float_as_uint(f);
    return (u & 0x80000000u) ? ~u : (u | 0x80000000u);
}
__device__ __forceinline__ float funord(unsigned u) {
    return (u & 0x80000000u) ? __uint_as_float(u ^ 0x80000000u)
                             : __uint_as_float(~u);
}

/* E[n,k] = exp(-dc/eps) in f64 range, computed with EX2 fast path.
   Relative error ~2.4e-7 which is far below the argmax decision scale. */
__device__ __forceinline__ double calcE(float c, float mid, float amp) {
    float t  = 1.0f - c;
    float d  = t / 0.2f;               /* matches reference f32 divide */
    float dc = (d - mid) / amp;        /* matches reference f32 ops    */
    double z  = (-(double)dc) / 0.005; /* z in (-200, 200)             */
    double t2 = z * 1.4426950408889634074;   /* log2(e) */
    double nn = rint(t2);
    float  f  = (float)(t2 - nn);            /* |f| <= 0.5, exact sub  */
    double p  = (double)exp2f(f);            /* MUFU.EX2 based          */
    long long bits = __double_as_longlong(p) + (((long long)nn) << 52);
    return __longlong_as_double(bits);
}

/* ---------------- kernels --------------------------------------------------- */

__global__ void k_init() {
    int i = blockIdx.x * blockDim.x + threadIdx.x;
    if (i < K_CB) g_u[i] = 0.0;
    if (i == 0) { g_omin = 0xFFFFFFFFu; g_omax = 0u; g_loss = 0.0; }
}

/* L2 normalize rows of length 128; one warp per row. isX -> g_xn else g_cn */
__global__ void k_norm(const float* __restrict__ in, int rows, int isX) {
    int w    = (blockIdx.x * blockDim.x + threadIdx.x) >> 5;
    int lane = threadIdx.x & 31;
    if (w >= rows) return;
    float* out = isX ? g_xn : g_cn;
    const float* r = in + (size_t)w * D_DIM;
    float v0 = r[lane], v1 = r[lane + 32], v2 = r[lane + 64], v3 = r[lane + 96];
    float s = v0 * v0 + v1 * v1 + v2 * v2 + v3 * v3;
    #pragma unroll
    for (int off = 16; off; off >>= 1) s += __shfl_xor_sync(0xFFFFFFFFu, s, off);
    float nrm = sqrtf(s);
    float den = fmaxf(nrm, 1e-12f);
    float* o = out + (size_t)w * D_DIM;
    o[lane]      = v0 / den;
    o[lane + 32] = v1 / den;
    o[lane + 64] = v2 / den;
    o[lane + 96] = v3 / den;
}

/* cos[n,k] = xn[n,:] . cn[k,:]  — 128x128 tile per block, 8x8 per thread */
__global__ __launch_bounds__(256) void k_gemm() {
    __shared__ float As[32][132];
    __shared__ float Bs[32][132];
    int k0 = blockIdx.x * 128;
    int n0 = blockIdx.y * 128;
    int tid = threadIdx.x;
    float acc[8][8];
    #pragma unroll
    for (int i = 0; i < 8; i++)
        #pragma unroll
        for (int j = 0; j < 8; j++) acc[i][j] = 0.0f;

    for (int d0 = 0; d0 < 128; d0 += 32) {
        #pragma unroll
        for (int i = 0; i < 16; i++) {
            int lin = tid + i * 256;
            int m   = lin >> 5;
            int dd  = lin & 31;
            As[dd][m] = g_xn[(size_t)(n0 + m) * 128 + d0 + dd];
            Bs[dd][m] = g_cn[(size_t)(k0 + m) * 128 + d0 + dd];
        }
        __syncthreads();
        int ty = tid >> 4, tx = tid & 15;
        #pragma unroll
        for (int dd = 0; dd < 32; dd++) {
            float ar[8], br[8];
            #pragma unroll
            for (int i = 0; i < 8; i++) ar[i] = As[dd][ty * 8 + i];
            #pragma unroll
            for (int j = 0; j < 8; j++) br[j] = Bs[dd][tx * 8 + j];
            #pragma unroll
            for (int i = 0; i < 8; i++)
                #pragma unroll
                for (int j = 0; j < 8; j++) acc[i][j] += ar[i] * br[j];
        }
        __syncthreads();
    }
    int ty = tid >> 4, tx = tid & 15;
    #pragma unroll
    for (int i = 0; i < 8; i++) {
        size_t row = (size_t)(n0 + ty * 8 + i) * 1024 + k0 + tx * 8;
        #pragma unroll
        for (int j = 0; j < 8; j++) g_cos[row + j] = acc[i][j];
    }
}

/* per-row logsumexp of cos/0.2 + global min/max of cos; one warp per row */
__global__ __launch_bounds__(256) void k_mml() {
    int gw   = (blockIdx.x * blockDim.x + threadIdx.x) >> 5;
    int lane = threadIdx.x & 31;
    int warp = threadIdx.x >> 5;
    float cmx = -3.4e38f, cmn = 3.4e38f;
    if (gw < N_PTS) {
        const float4* row = (const float4*)(g_cos + (size_t)gw * 1024);
        float c[32];
        #pragma unroll
        for (int j = 0; j < 8; j++) {
            float4 v = row[lane + j * 32];
            c[j * 4 + 0] = v.x; c[j * 4 + 1] = v.y;
            c[j * 4 + 2] = v.z; c[j * 4 + 3] = v.w;
        }
        #pragma unroll
        for (int i = 0; i < 32; i++) { cmx = fmaxf(cmx, c[i]); cmn = fminf(cmn, c[i]); }
        float wmx = cmx, wmn = cmn;
        #pragma unroll
        for (int off = 16; off; off >>= 1) {
            wmx = fmaxf(wmx, __shfl_xor_sync(0xFFFFFFFFu, wmx, off));
            wmn = fminf(wmn, __shfl_xor_sync(0xFFFFFFFFu, wmn, off));
        }
        float m = wmx / 0.2f;
        float s = 0.0f;
        #pragma unroll
        for (int i = 0; i < 32; i++) s += expf(c[i] / 0.2f - m);
        #pragma unroll
        for (int off = 16; off; off >>= 1) s += __shfl_xor_sync(0xFFFFFFFFu, s, off);
        if (lane == 0) g_lse[gw] = m + logf(s);
        cmx = wmx; cmn = wmn;
    }
    __shared__ float smx[8], smn[8];
    if (lane == 0) { smx[warp] = cmx; smn[warp] = cmn; }
    __syncthreads();
    if (threadIdx.x == 0) {
        float bmx = smx[0], bmn = smn[0];
        for (int i = 1; i < 8; i++) { bmx = fmaxf(bmx, smx[i]); bmn = fminf(bmn, smn[i]); }
        atomicMax(&g_omax, ford(bmx));
        atomicMin(&g_omin, ford(bmn));
    }
}

__global__ void k_mid() {
    float cmin = funord(g_omin), cmax = funord(g_omax);
    float dmax = (1.0f - cmin) / 0.2f;   /* monotone decreasing map */
    float dmin = (1.0f - cmax) / 0.2f;
    float mid  = (dmax + dmin) / 2.0f;
    float amp  = fmaxf(dmax - mid + 1e-5f, 1e-5f);
    g_mid = mid; g_amp = amp;
}

/* u[k] += sum_n E[n,k] * (WB ? b[n] : 1) ; 64 rows per block, 4 cols/thread */
template <bool WB>
__global__ __launch_bounds__(256) void k_sumE() {
    int t  = threadIdx.x;
    int r0 = blockIdx.x * 64;
    float mid = g_mid, amp = g_amp;
    double a0 = 0, a1 = 0, a2 = 0, a3 = 0;
    for (int r = 0; r < 64; r++) {
        int n = r0 + r;
        double w = WB ? g_b[n] : 1.0;
        const float* row = g_cos + (size_t)n * 1024;
        double e0 = calcE(row[t],       mid, amp);
        double e1 = calcE(row[t + 256], mid, amp);
        double e2 = calcE(row[t + 512], mid, amp);
        double e3 = calcE(row[t + 768], mid, amp);
        if (WB) { e0 *= w; e1 *= w; e2 *= w; e3 *= w; }
        a0 += e0; a1 += e1; a2 += e2; a3 += e3;
    }
    atomicAdd(&g_u[t],       a0);
    atomicAdd(&g_u[t + 256], a1);
    atomicAdd(&g_u[t + 512], a2);
    atomicAdd(&g_u[t + 768], a3);
}

/* a[k] = 1/(K*u[k]); also clears u for next pass */
__global__ void k_a() {
    int k = threadIdx.x;
    g_a[k] = 1.0 / (1024.0 * g_u[k]);
    g_u[k] = 0.0;
}

/* b[n] = 1/(N * sum_k E[n,k]*a[k]) ; warp per row, 4 rows per warp */
__global__ __launch_bounds__(256) void k_colsum() {
    __shared__ double sa[1024];
    int tid = threadIdx.x;
    for (int i = tid; i < 1024; i += 256) sa[i] = g_a[i];
    __syncthreads();
    int warp = tid >> 5, lane = tid & 31;
    float mid = g_mid, amp = g_amp;
    int n0 = blockIdx.x * 32 + warp * 4;
    for (int r = 0; r < 4; r++) {
        int n = n0 + r;
        const float* row = g_cos + (size_t)n * 1024;
        double s = 0.0;
        #pragma unroll 8
        for (int j = 0; j < 32; j++) {
            int k = lane + j * 32;
            s += calcE(row[k], mid, amp) * sa[k];
        }
        #pragma unroll
        for (int off = 16; off; off >>= 1) s += __shfl_xor_sync(0xFFFFFFFFu, s, off);
        if (lane == 0) g_b[n] = 1.0 / (32768.0 * s);
    }
}

/* idx[n] = argmax_k E[n,k]*a[k] (first max wins); accumulate loss */
__global__ __launch_bounds__(256) void k_argmax() {
    __shared__ double sa[1024];
    __shared__ double lpart[8];
    int tid = threadIdx.x;
    for (int i = tid; i < 1024; i += 256) sa[i] = g_a[i];
    __syncthreads();
    int warp = tid >> 5, lane = tid & 31;
    float mid = g_mid, amp = g_amp;
    int n0 = blockIdx.x * 32 + warp * 4;
    double lsum = 0.0;
    for (int r = 0; r < 4; r++) {
        int n = n0 + r;
        const float* row = g_cos + (size_t)n * 1024;
        double bv = -1.0;  /* all values positive */
        int    bk = 0;
        #pragma unroll 8
        for (int j = 0; j < 32; j++) {
            int k = lane + j * 32;
            double v = calcE(row[k], mid, amp) * sa[k];
            if (v > bv) { bv = v; bk = k; }
        }
        #pragma unroll
        for (int off = 16; off; off >>= 1) {
            double ov = __shfl_down_sync(0xFFFFFFFFu, bv, off);
            int    ok = __shfl_down_sync(0xFFFFFFFFu, bk, off);
            if (ov > bv || (ov == bv && ok < bk)) { bv = ov; bk = ok; }
        }
        if (lane == 0) {
            g_idx[n] = bk;
            float li = row[bk] / 0.2f;
            lsum += (double)(g_lse[n] - li);
        }
    }
    if (lane == 0) lpart[warp] = lsum;
    __syncthreads();
    if (tid == 0) {
        double t = 0.0;
        for (int i = 0; i < 8; i++) t += lpart[i];
        atomicAdd(&g_loss, t);
    }
}

/* out = [x_q (N*D) | loss (1) | indices (N)] as float32 */
__global__ void k_out(const float* __restrict__ codebook,
                      float* __restrict__ out, int out_size) {
    int i = blockIdx.x * blockDim.x + threadIdx.x;
    if (i >= out_size) return;
    if (i < ND) {
        int n = i >> 7;
        out[i] = codebook[(size_t)g_idx[n] * 128 + (i & 127)];
    } else if (i == ND) {
        out[i] = (float)(g_loss / 32768.0);
    } else {
        int j = i - ND - 1;
        out[i] = (j < N_PTS) ? (float)g_idx[j] : 0.0f;
    }
}

/* ---------------- launch ---------------------------------------------------- */
extern "C" void kernel_launch(void* const* d_in, const int* in_sizes, int n_in,
                              void* d_out, int out_size) {
    const float* x  = (const float*)d_in[0];
    const float* cb = (const float*)d_in[1];
    if (n_in >= 2 && in_sizes[0] == K_CB * D_DIM && in_sizes[1] == ND) {
        const float* t = x; x = cb; cb = t;  /* defensive input-order swap */
    }
    float* out = (float*)d_out;

    k_init<<<(K_CB + 255) / 256, 256>>>();
    k_norm<<<(K_CB * 32 + 255) / 256, 256>>>(cb, K_CB, 0);
    k_norm<<<(N_PTS * 32 + 255) / 256, 256>>>(x, N_PTS, 1);

    dim3 ggrid(K_CB / 128, N_PTS / 128);
    k_gemm<<<ggrid, 256>>>();

    k_mml<<<N_PTS / 8, 256>>>();
    k_mid<<<1, 1>>>();

    /* Sinkhorn: iter1 row, iter1 col, iter2 row, iter2 col, iter3 row */
    k_sumE<false><<<N_PTS / 64, 256>>>();
    k_a<<<1, 1024>>>();
    k_colsum<<<N_PTS / 32, 256>>>();
    k_sumE<true><<<N_PTS / 64, 256>>>();
    k_a<<<1, 1024>>>();
    k_colsum<<<N_PTS / 32, 256>>>();
    k_sumE<true><<<N_PTS / 64, 256>>>();
    k_a<<<1, 1024>>>();

    k_argmax<<<N_PTS / 32, 256>>>();

    int ob = (out_size + 255) / 256;
    if (ob > 0) k_out<<<ob, 256>>>(cb, out, out_size);
}

// round 4
// speedup vs baseline: 7.3698x; 7.3698x over previous
#include <cuda_runtime.h>
#include <math.h>
#include <stdint.h>

#define N_PTS 32768
#define D_DIM 128
#define K_CB  1024
#define ND    (N_PTS*D_DIM)        /* 4194304  */
#define NK    ((size_t)N_PTS*K_CB) /* 33554432 */

/* ---------------- persistent device scratch (no allocs allowed) ------------- */
__device__ float     g_xn[ND];            /* normalized x          16 MB  */
__device__ float     g_cn[K_CB*D_DIM];    /* normalized codebook   512 KB */
__device__ float     g_cos[N_PTS*K_CB];   /* cosine sims           134 MB */
__device__ double    g_E[N_PTS*K_CB];     /* exp(-dc/eps) f64      268 MB */
__device__ float     g_lse[N_PTS];        /* per-row logsumexp of logits  */
__device__ double    g_u[K_CB];           /* row-sum accumulator          */
__device__ double    g_a[K_CB];           /* row scaling factor           */
__device__ double    g_b[N_PTS];          /* col scaling factor           */
__device__ long long g_afix[K_CB];        /* log2(a3)*2^20 fixed point    */
__device__ unsigned  g_omin, g_omax;      /* ordered-uint encoded min/max */
__device__ float     g_mid, g_amp;        /* centering constants          */
__device__ double    g_loss;              /* loss accumulator             */
__device__ int       g_idx[N_PTS];        /* argmax indices               */

/* ---------------- helpers --------------------------------------------------- */
__device__ __forceinline__ unsigned ford(float f) {
    unsigned u = __float_as_uint(f);
    return (u & 0x80000000u) ? ~u : (u | 0x80000000u);
}
__device__ __forceinline__ float funord(unsigned u) {
    return (u & 0x80000000u) ? __uint_as_float(u ^ 0x80000000u)
                             : __uint_as_float(~u);
}

/* Cd = -log2(e)/0.005 split into two floats (exact to ~2^-45 rel) */
#define CD_FULL (-288.53900817779268)
#define CHI ((float)CD_FULL)
#define CLO ((float)(CD_FULL - (double)(float)CD_FULL))

/* f32 chain identical to the passing round-2 kernel (bit-exact),
   then t2 = dc*Cd as a two-float product. */
__device__ __forceinline__ void t2_split(float c, float mid, float amp,
                                         float& hi, float& lo) {
    float t  = 1.0f - c;
    float d  = t / 0.2f;
    float dc = (d - mid) / amp;
    hi = dc * CHI;
    lo = fmaf(dc, CHI, -hi);   /* exact product residual */
    lo = fmaf(dc, CLO, lo);
}

/* E = 2^t2 computed with ZERO fp64 arithmetic: exp2f on the fraction,
   exponent spliced in with integer ops.  rel err ~2.4e-7. */
__device__ __forceinline__ double calcE(float c, float mid, float amp) {
    float hi, lo;
    t2_split(c, mid, amp, hi, lo);
    float big = hi + 12582912.0f;                 /* 2^23+2^22 round trick */
    int   nn  = __float_as_int(big) - __float_as_int(12582912.0f);
    float nnf = big - 12582912.0f;
    float f   = (hi - nnf) + lo;                  /* |f| <= ~0.5 */
    float p   = exp2f(f);                         /* p in [0.70, 1.42) */
    unsigned long long eb =
        ((unsigned long long)__float_as_uint(p) << 29) +
        ((unsigned long long)(unsigned)(896 + nn) << 52);
    return __longlong_as_double((long long)eb);
}

/* ---------------- kernels --------------------------------------------------- */

__global__ void k_init() {
    int i = blockIdx.x * blockDim.x + threadIdx.x;
    if (i < K_CB) g_u[i] = 0.0;
    if (i == 0) { g_omin = 0xFFFFFFFFu; g_omax = 0u; g_loss = 0.0; }
}

/* L2 normalize rows of length 128; one warp per row */
__global__ void k_norm(const float* __restrict__ in, int rows, int isX) {
    int w    = (blockIdx.x * blockDim.x + threadIdx.x) >> 5;
    int lane = threadIdx.x & 31;
    if (w >= rows) return;
    float* out = isX ? g_xn : g_cn;
    const float* r = in + (size_t)w * D_DIM;
    float v0 = r[lane], v1 = r[lane + 32], v2 = r[lane + 64], v3 = r[lane + 96];
    float s = v0 * v0 + v1 * v1 + v2 * v2 + v3 * v3;
    #pragma unroll
    for (int off = 16; off; off >>= 1) s += __shfl_xor_sync(0xFFFFFFFFu, s, off);
    float den = fmaxf(sqrtf(s), 1e-12f);
    float* o = out + (size_t)w * D_DIM;
    o[lane]      = v0 / den;
    o[lane + 32] = v1 / den;
    o[lane + 64] = v2 / den;
    o[lane + 96] = v3 / den;
}

/* cos[n,k] = xn[n,:] . cn[k,:]  — 128x128 tile, 8x8/thread, float4 smem */
__global__ __launch_bounds__(256) void k_gemm() {
    __shared__ float As[32][132];
    __shared__ float Bs[32][132];
    int k0 = blockIdx.x * 128;
    int n0 = blockIdx.y * 128;
    int tid = threadIdx.x;
    float acc[8][8];
    #pragma unroll
    for (int i = 0; i < 8; i++)
        #pragma unroll
        for (int j = 0; j < 8; j++) acc[i][j] = 0.0f;

    int ty = tid >> 4, tx = tid & 15;
    for (int d0 = 0; d0 < 128; d0 += 32) {
        #pragma unroll
        for (int i = 0; i < 16; i++) {
            int lin = tid + i * 256;
            int m   = lin >> 5;
            int dd  = lin & 31;
            As[dd][m] = g_xn[(size_t)(n0 + m) * 128 + d0 + dd];
            Bs[dd][m] = g_cn[(size_t)(k0 + m) * 128 + d0 + dd];
        }
        __syncthreads();
        #pragma unroll
        for (int dd = 0; dd < 32; dd++) {
            float4 a0 = *(const float4*)&As[dd][ty * 8];
            float4 a1 = *(const float4*)&As[dd][ty * 8 + 4];
            float4 b0 = *(const float4*)&Bs[dd][tx * 4];
            float4 b1 = *(const float4*)&Bs[dd][64 + tx * 4];
            float ar[8] = {a0.x,a0.y,a0.z,a0.w,a1.x,a1.y,a1.z,a1.w};
            float br[8] = {b0.x,b0.y,b0.z,b0.w,b1.x,b1.y,b1.z,b1.w};
            #pragma unroll
            for (int i = 0; i < 8; i++)
                #pragma unroll
                for (int j = 0; j < 8; j++) acc[i][j] += ar[i] * br[j];
        }
        __syncthreads();
    }
    #pragma unroll
    for (int i = 0; i < 8; i++) {
        size_t row = (size_t)(n0 + ty * 8 + i) * 1024;
        float4 v0 = {acc[i][0], acc[i][1], acc[i][2], acc[i][3]};
        float4 v1 = {acc[i][4], acc[i][5], acc[i][6], acc[i][7]};
        *(float4*)&g_cos[row + k0 + tx * 4]      = v0;
        *(float4*)&g_cos[row + k0 + 64 + tx * 4] = v1;
    }
}

/* per-row logsumexp of cos/0.2 + global min/max of cos; one warp per row */
__global__ __launch_bounds__(256) void k_mml() {
    int gw   = (blockIdx.x * blockDim.x + threadIdx.x) >> 5;
    int lane = threadIdx.x & 31;
    int warp = threadIdx.x >> 5;
    float cmx = -3.4e38f, cmn = 3.4e38f;
    if (gw < N_PTS) {
        const float4* row = (const float4*)(g_cos + (size_t)gw * 1024);
        float c[32];
        #pragma unroll
        for (int j = 0; j < 8; j++) {
            float4 v = row[lane + j * 32];
            c[j * 4 + 0] = v.x; c[j * 4 + 1] = v.y;
            c[j * 4 + 2] = v.z; c[j * 4 + 3] = v.w;
        }
        #pragma unroll
        for (int i = 0; i < 32; i++) { cmx = fmaxf(cmx, c[i]); cmn = fminf(cmn, c[i]); }
        float wmx = cmx, wmn = cmn;
        #pragma unroll
        for (int off = 16; off; off >>= 1) {
            wmx = fmaxf(wmx, __shfl_xor_sync(0xFFFFFFFFu, wmx, off));
            wmn = fminf(wmn, __shfl_xor_sync(0xFFFFFFFFu, wmn, off));
        }
        float m = wmx / 0.2f;
        float s = 0.0f;
        #pragma unroll
        for (int i = 0; i < 32; i++) s += expf(c[i] / 0.2f - m);
        #pragma unroll
        for (int off = 16; off; off >>= 1) s += __shfl_xor_sync(0xFFFFFFFFu, s, off);
        if (lane == 0) g_lse[gw] = m + logf(s);
        cmx = wmx; cmn = wmn;
    }
    __shared__ float smx[8], smn[8];
    if (lane == 0) { smx[warp] = cmx; smn[warp] = cmn; }
    __syncthreads();
    if (threadIdx.x == 0) {
        float bmx = smx[0], bmn = smn[0];
        for (int i = 1; i < 8; i++) { bmx = fmaxf(bmx, smx[i]); bmn = fminf(bmn, smn[i]); }
        atomicMax(&g_omax, ford(bmx));
        atomicMin(&g_omin, ford(bmn));
    }
}

__global__ void k_mid() {
    float cmin = funord(g_omin), cmax = funord(g_omax);
    float dmax = (1.0f - cmin) / 0.2f;
    float dmin = (1.0f - cmax) / 0.2f;
    float mid  = (dmax + dmin) / 2.0f;
    float amp  = fmaxf(dmax - mid + 1e-5f, 1e-5f);
    g_mid = mid; g_amp = amp;
}

/* fused: compute + store E, accumulate u1[k] = sum_n E[n,k] */
__global__ __launch_bounds__(256) void k_e1() {
    int t  = threadIdx.x;
    int r0 = blockIdx.x * 64;
    float mid = g_mid, amp = g_amp;
    double a0 = 0, a1 = 0, a2 = 0, a3 = 0;
    for (int r = 0; r < 64; r++) {
        size_t base = (size_t)(r0 + r) * 1024;
        double e0 = calcE(g_cos[base + t],       mid, amp);
        double e1 = calcE(g_cos[base + t + 256], mid, amp);
        double e2 = calcE(g_cos[base + t + 512], mid, amp);
        double e3 = calcE(g_cos[base + t + 768], mid, amp);
        g_E[base + t]       = e0;
        g_E[base + t + 256] = e1;
        g_E[base + t + 512] = e2;
        g_E[base + t + 768] = e3;
        a0 += e0; a1 += e1; a2 += e2; a3 += e3;
    }
    atomicAdd(&g_u[t],       a0);
    atomicAdd(&g_u[t + 256], a1);
    atomicAdd(&g_u[t + 512], a2);
    atomicAdd(&g_u[t + 768], a3);
}

/* a[k] = 1/(K*u[k]); clears u for next pass */
__global__ void k_a() {
    int k = threadIdx.x;
    g_a[k] = 1.0 / (1024.0 * g_u[k]);
    g_u[k] = 0.0;
}

/* b[n] = 1/(N * sum_k E[n,k]*a[k]); warp per row, 4 rows per warp */
__global__ __launch_bounds__(256) void k_colsum() {
    __shared__ double sa[1024];
    int tid = threadIdx.x;
    for (int i = tid; i < 1024; i += 256) sa[i] = g_a[i];
    __syncthreads();
    int warp = tid >> 5, lane = tid & 31;
    int n0 = blockIdx.x * 32 + warp * 4;
    for (int r = 0; r < 4; r++) {
        int n = n0 + r;
        const double* row = g_E + (size_t)n * 1024;
        double s0 = 0, s1 = 0, s2 = 0, s3 = 0;
        #pragma unroll
        for (int j = 0; j < 32; j += 4) {
            s0 = fma(row[lane + (j + 0) * 32], sa[lane + (j + 0) * 32], s0);
            s1 = fma(row[lane + (j + 1) * 32], sa[lane + (j + 1) * 32], s1);
            s2 = fma(row[lane + (j + 2) * 32], sa[lane + (j + 2) * 32], s2);
            s3 = fma(row[lane + (j + 3) * 32], sa[lane + (j + 3) * 32], s3);
        }
        double s = (s0 + s1) + (s2 + s3);
        #pragma unroll
        for (int off = 16; off; off >>= 1) s += __shfl_xor_sync(0xFFFFFFFFu, s, off);
        if (lane == 0) g_b[n] = 1.0 / (32768.0 * s);
    }
}

/* u[k] += sum_n E[n,k]*b[n] ; reads precomputed E, 1 DFMA per element */
__global__ __launch_bounds__(256) void k_sumE() {
    int t  = threadIdx.x;
    int r0 = blockIdx.x * 64;
    double a0 = 0, a1 = 0, a2 = 0, a3 = 0;
    for (int r = 0; r < 64; r++) {
        int n = r0 + r;
        double w = g_b[n];
        const double* row = g_E + (size_t)n * 1024;
        a0 = fma(row[t],       w, a0);
        a1 = fma(row[t + 256], w, a1);
        a2 = fma(row[t + 512], w, a2);
        a3 = fma(row[t + 768], w, a3);
    }
    atomicAdd(&g_u[t],       a0);
    atomicAdd(&g_u[t + 256], a1);
    atomicAdd(&g_u[t + 512], a2);
    atomicAdd(&g_u[t + 768], a3);
}

/* afix[k] = round(log2(a3_k) * 2^20) for integer-only argmax */
__global__ void k_afix() {
    int k = threadIdx.x;
    double a = 1.0 / (1024.0 * g_u[k]);
    g_afix[k] = llround(log2(a) * 1048576.0);
}

/* argmax in log2 fixed-point: key = round(t2*2^20) + afix[k].  No fp64. */
__global__ __launch_bounds__(256) void k_argmax() {
    __shared__ long long sA[1024];
    __shared__ double lpart[8];
    int tid = threadIdx.x;
    for (int i = tid; i < 1024; i += 256) sA[i] = g_afix[i];
    __syncthreads();
    int warp = tid >> 5, lane = tid & 31;
    float mid = g_mid, amp = g_amp;
    int n0 = blockIdx.x * 32 + warp * 4;
    double lsum = 0.0;
    for (int r = 0; r < 4; r++) {
        int n = n0 + r;
        const float* row = g_cos + (size_t)n * 1024;
        long long bkey = 0x8000000000000000LL;
        int bk = 0;
        #pragma unroll 8
        for (int j = 0; j < 32; j++) {
            int k = lane + j * 32;
            float hi, lo;
            t2_split(row[k], mid, amp, hi, lo);
            long long key = __float2ll_rn(hi * 1048576.0f)
                          + __float2ll_rn(lo * 1048576.0f)
                          + sA[k];
            if (key > bkey) { bkey = key; bk = k; }   /* first max wins */
        }
        #pragma unroll
        for (int off = 16; off; off >>= 1) {
            long long ov = __shfl_down_sync(0xFFFFFFFFu, bkey, off);
            int       ok = __shfl_down_sync(0xFFFFFFFFu, bk,   off);
            if (ov > bkey || (ov == bkey && ok < bk)) { bkey = ov; bk = ok; }
        }
        if (lane == 0) {
            g_idx[n] = bk;
            float li = row[bk] / 0.2f;
            lsum += (double)(g_lse[n] - li);
        }
    }
    if (lane == 0) lpart[warp] = lsum;
    __syncthreads();
    if (tid == 0) {
        double t = 0.0;
        for (int i = 0; i < 8; i++) t += lpart[i];
        atomicAdd(&g_loss, t);
    }
}

/* out = [x_q (N*D) | loss (1) | indices (N)] as float32 */
__global__ void k_out(const float* __restrict__ codebook,
                      float* __restrict__ out, int out_size) {
    int i = blockIdx.x * blockDim.x + threadIdx.x;
    if (i >= out_size) return;
    if (i < ND) {
        int n = i >> 7;
        out[i] = codebook[(size_t)g_idx[n] * 128 + (i & 127)];
    } else if (i == ND) {
        out[i] = (float)(g_loss / 32768.0);
    } else {
        int j = i - ND - 1;
        out[i] = (j < N_PTS) ? (float)g_idx[j] : 0.0f;
    }
}

/* ---------------- launch ---------------------------------------------------- */
extern "C" void kernel_launch(void* const* d_in, const int* in_sizes, int n_in,
                              void* d_out, int out_size) {
    const float* x  = (const float*)d_in[0];
    const float* cb = (const float*)d_in[1];
    if (n_in >= 2 && in_sizes[0] == K_CB * D_DIM && in_sizes[1] == ND) {
        const float* t = x; x = cb; cb = t;
    }
    float* out = (float*)d_out;

    k_init<<<(K_CB + 255) / 256, 256>>>();
    k_norm<<<(K_CB * 32 + 255) / 256, 256>>>(cb, K_CB, 0);
    k_norm<<<(N_PTS * 32 + 255) / 256, 256>>>(x, N_PTS, 1);

    dim3 ggrid(K_CB / 128, N_PTS / 128);
    k_gemm<<<ggrid, 256>>>();

    k_mml<<<N_PTS / 8, 256>>>();
    k_mid<<<1, 1>>>();

    /* Sinkhorn: E+u1 fused, then a/colsum/sumE chain */
    k_e1<<<N_PTS / 64, 256>>>();
    k_a<<<1, 1024>>>();
    k_colsum<<<N_PTS / 32, 256>>>();   /* b1 */
    k_sumE<<<N_PTS / 64, 256>>>();     /* u2 */
    k_a<<<1, 1024>>>();
    k_colsum<<<N_PTS / 32, 256>>>();   /* b2 */
    k_sumE<<<N_PTS / 64, 256>>>();     /* u3 */
    k_afix<<<1, 1024>>>();

    k_argmax<<<N_PTS / 32, 256>>>();

    int ob = (out_size + 255) / 256;
    if (ob > 0) k_out<<<ob, 256>>>(cb, out, out_size);
}